// round 15
// baseline (speedup 1.0000x reference)
#include <cuda_runtime.h>
#include <cuda_fp16.h>
#include <math.h>
#include <stdint.h>

#define T_TOT 1154
#define C_DIM 768
#define NHEAD 12
#define NE (T_TOT * C_DIM)
#define QKV_PART_STRIDE 2658816     // 1154*2304

// weight offsets (elements)
#define W_QKV_OFF 0
#define W_PROJ_OFF 21233664
#define W_FC1_OFF  28311552
#define W_FC2_OFF  56623104
#define W_TOTAL    84934656

// ---------------- device scratch ----------------
__device__ float g_x[NE];
__device__ float g_loc[NE];
__device__ float g_part[3 * QKV_PART_STRIDE];   // 7.97M floats; holds 3x QKV partials or 6x NE partials
__device__ __half g_w[W_TOTAL];
__device__ __half g_sh[NE];
__device__ __half g_sl[NE];
__device__ __half g_mh[NE * 4];
__device__ __half g_ml[NE * 4];
__device__ __half g_qh[NHEAD * T_TOT * 64];
__device__ __half g_ql[NHEAD * T_TOT * 64];
__device__ __half g_kh[NHEAD * T_TOT * 64];
__device__ __half g_vh[NHEAD * T_TOT * 64];

// ---------------- helpers ----------------
__device__ __forceinline__ float block_sum_256(float v, float* sh) {
    #pragma unroll
    for (int off = 16; off; off >>= 1) v += __shfl_xor_sync(0xffffffffu, v, off);
    __syncthreads();
    if ((threadIdx.x & 31) == 0) sh[threadIdx.x >> 5] = v;
    __syncthreads();
    float r = 0.f;
    #pragma unroll
    for (int i = 0; i < 8; i++) r += sh[i];
    return r;
}

__device__ __forceinline__ uint32_t smem_u32(const void* p) {
    uint32_t a;
    asm("{ .reg .u64 t; cvta.to.shared.u64 t, %1; cvt.u32.u64 %0, t; }" : "=r"(a) : "l"(p));
    return a;
}

__device__ __forceinline__ void ldm4(uint32_t* r, uint32_t addr) {
    asm volatile("ldmatrix.sync.aligned.m8n8.x4.shared.b16 {%0,%1,%2,%3}, [%4];"
                 : "=r"(r[0]), "=r"(r[1]), "=r"(r[2]), "=r"(r[3]) : "r"(addr));
}

__device__ __forceinline__ void ldm4t(uint32_t* r, uint32_t addr) {
    asm volatile("ldmatrix.sync.aligned.m8n8.x4.trans.shared.b16 {%0,%1,%2,%3}, [%4];"
                 : "=r"(r[0]), "=r"(r[1]), "=r"(r[2]), "=r"(r[3]) : "r"(addr));
}

__device__ __forceinline__ void mma_hf(float* d, const uint32_t* a, uint32_t b0, uint32_t b1) {
    asm volatile(
        "mma.sync.aligned.m16n8k16.row.col.f32.f16.f16.f32 "
        "{%0,%1,%2,%3}, {%4,%5,%6,%7}, {%8,%9}, {%0,%1,%2,%3};"
        : "+f"(d[0]), "+f"(d[1]), "+f"(d[2]), "+f"(d[3])
        : "r"(a[0]), "r"(a[1]), "r"(a[2]), "r"(a[3]), "r"(b0), "r"(b1));
}

__device__ __forceinline__ uint32_t pack_hf2(float a, float b) {
    __half ha = __float2half_rn(a), hb = __float2half_rn(b);
    return (uint32_t)__half_as_ushort(ha) | ((uint32_t)__half_as_ushort(hb) << 16);
}

// ---------------- weight conversion ----------------
__global__ void convall_kernel(const float* __restrict__ qkv_w, const float* __restrict__ pw,
                               const float* __restrict__ f1w, const float* __restrict__ f2w,
                               __half* __restrict__ dw) {
    int i = blockIdx.x * 256 + threadIdx.x;
    if (i >= W_TOTAL / 4) return;
    const float* src;
    int local;
    if (i < W_PROJ_OFF / 4)      { src = qkv_w; local = i; }
    else if (i < W_FC1_OFF / 4)  { src = pw;    local = i - W_PROJ_OFF / 4; }
    else if (i < W_FC2_OFF / 4)  { src = f1w;   local = i - W_FC1_OFF / 4; }
    else                         { src = f2w;   local = i - W_FC2_OFF / 4; }
    float4 x = ((const float4*)src)[local];
    uint2 hv;
    hv.x = pack_hf2(x.x, x.y);
    hv.y = pack_hf2(x.z, x.w);
    ((uint2*)dw)[i] = hv;
}

// ---------------- init ----------------
__global__ void init_x_kernel(const float* __restrict__ xin, const float* __restrict__ cam) {
    int i = blockIdx.x * 256 + threadIdx.x;
    if (i >= NE) return;
    int t = i / C_DIM, c = i - t * C_DIM;
    float v;
    if (t == 0) v = cam[c];
    else if (t == 577) v = cam[C_DIM + c];
    else v = xin[i];
    g_x[i] = v;
}

// ---------------- LayerNorm (layer 0 only) ----------------
__global__ __launch_bounds__(256) void ln_kernel(const float* __restrict__ x,
                                                 __half* __restrict__ yh, __half* __restrict__ yl,
                                                 const float* __restrict__ w, const float* __restrict__ b) {
    __shared__ float sh[8];
    int t = blockIdx.x, tid = threadIdx.x;
    const float* xr = x + (size_t)t * C_DIM;
    float v0 = xr[tid], v1 = xr[tid + 256], v2 = xr[tid + 512];
    float mean = block_sum_256(v0 + v1 + v2, sh) * (1.f / 768.f);
    float d0 = v0 - mean, d1 = v1 - mean, d2 = v2 - mean;
    float var = block_sum_256(d0 * d0 + d1 * d1 + d2 * d2, sh) * (1.f / 768.f);
    float rstd = rsqrtf(var + 1e-6f);
    float o0 = d0 * rstd * w[tid]       + b[tid];
    float o1 = d1 * rstd * w[tid + 256] + b[tid + 256];
    float o2 = d2 * rstd * w[tid + 512] + b[tid + 512];
    size_t base = (size_t)t * C_DIM + tid;
    __half h0 = __float2half_rn(o0);
    __half h1 = __float2half_rn(o1);
    __half h2 = __float2half_rn(o2);
    yh[base] = h0;       yl[base]       = __float2half_rn(o0 - __half2float(h0));
    yh[base + 256] = h1; yl[base + 256] = __float2half_rn(o1 - __half2float(h1));
    yh[base + 512] = h2; yl[base + 512] = __float2half_rn(o2 - __half2float(h2));
}

// ---------------- fused combine + residual + LN (sums ns partials) ----------------
__global__ __launch_bounds__(256) void combine_ln_kernel(
    float* __restrict__ x, const float* __restrict__ part,
    const float* __restrict__ bias, const float* __restrict__ gamma, int ns,
    const float* __restrict__ w, const float* __restrict__ b,
    __half* __restrict__ yh, __half* __restrict__ yl,
    float* __restrict__ loc)
{
    __shared__ float sh[8];
    int t = blockIdx.x, tid = threadIdx.x;
    float v[3];
    #pragma unroll
    for (int j = 0; j < 3; j++) {
        int c = tid + j * 256;
        size_t idx = (size_t)t * C_DIM + c;
        float s = part[idx];
        for (int p = 1; p < ns; p++) s += part[(size_t)p * NE + idx];
        float xv = x[idx] + gamma[c] * (s + bias[c]);
        x[idx] = xv;
        if (loc) loc[idx] = xv;
        v[j] = xv;
    }
    float mean = block_sum_256(v[0] + v[1] + v[2], sh) * (1.f / 768.f);
    float d0 = v[0] - mean, d1 = v[1] - mean, d2 = v[2] - mean;
    float var = block_sum_256(d0 * d0 + d1 * d1 + d2 * d2, sh) * (1.f / 768.f);
    float rstd = rsqrtf(var + 1e-6f);
    float o0 = d0 * rstd * w[tid]       + b[tid];
    float o1 = d1 * rstd * w[tid + 256] + b[tid + 256];
    float o2 = d2 * rstd * w[tid + 512] + b[tid + 512];
    size_t base = (size_t)t * C_DIM + tid;
    __half h0 = __float2half_rn(o0);
    __half h1 = __float2half_rn(o1);
    __half h2 = __float2half_rn(o2);
    yh[base] = h0;       yl[base]       = __float2half_rn(o0 - __half2float(h0));
    yh[base + 256] = h1; yl[base + 256] = __float2half_rn(o1 - __half2float(h1));
    yh[base + 512] = h2; yl[base + 512] = __float2half_rn(o2 - __half2float(h2));
}

// ---------------- plain combine (layer 11 fc2) ----------------
__global__ void combine_kernel(float* __restrict__ x, const float* __restrict__ part,
                               const float* __restrict__ bias, const float* __restrict__ gamma,
                               int ns) {
    int i = blockIdx.x * 256 + threadIdx.x;
    if (i >= NE) return;
    int c = i % C_DIM;
    float s = part[i];
    for (int p = 1; p < ns; p++) s += part[(size_t)p * NE + i];
    x[i] += gamma[c] * (s + bias[c]);
}

// ---------------- fp16 2-term GEMM: CTA 128 thr, tile 64x128, 2-stage, 4 CTAs/SM ----------------
#define SM_STRIDE 40
#define STAGE_ELE 10240
#define GEMM_SMEM 40960

__global__ __launch_bounds__(128, 4) void gemm_mma(
    const __half* __restrict__ Ah, const __half* __restrict__ Al,
    const __half* __restrict__ W,
    const float* __restrict__ bias,
    float* __restrict__ Cf, __half* __restrict__ Ch, __half* __restrict__ Cl,
    float* __restrict__ part,
    int M, int Nn, int K, int act, int nsplit)
{
    extern __shared__ __align__(16) uint16_t sm[];
    const int tid = threadIdx.x;
    const int wid = tid >> 5, lane = tid & 31;
    const int warpM = wid >> 1, warpN = wid & 1;
    const int bm = blockIdx.y * 64, bn = blockIdx.x * 128;
    const int kz = blockIdx.z;
    const int Kp = K / nsplit;
    const int kz0 = kz * Kp;
    const uint32_t sbase = smem_u32(sm);

    float acc[2][8][4];
    #pragma unroll
    for (int i = 0; i < 2; i++)
        #pragma unroll
        for (int j = 0; j < 8; j++)
            #pragma unroll
            for (int k = 0; k < 4; k++) acc[i][j][k] = 0.f;

    const int a_row = warpM * 32 + (lane & 15);
    const int a_kc  = (lane >> 4) * 8;
    const int b_row = warpN * 64 + ((lane >> 4) & 1) * 8 + (lane & 7);
    const int b_kc  = ((lane >> 3) & 1) * 8;

    const int NC = Kp >> 5;

    auto issue = [&](int c) {
        const int s = c & 1, k0 = kz0 + (c << 5);
        const uint32_t sb = sbase + (uint32_t)s * (STAGE_ELE * 2);
        #pragma unroll
        for (int it = 0; it < 8; it++) {
            int u = tid + (it << 7);
            const __half* gp;
            uint32_t sa;
            int sz = 16;
            if (u < 512) {
                int mat = u >> 8;
                int v = u & 255;
                int r = v >> 2, seg = (v & 3) << 3;
                int gr = bm + r;
                if (gr >= M) { sz = 0; gr = M - 1; }
                gp = (mat == 0 ? Ah : Al) + (size_t)gr * K + k0 + seg;
                sa = sb + (uint32_t)(mat * 2560 + r * SM_STRIDE + seg) * 2;
            } else {
                int v = u - 512;
                int r = v >> 2, seg = (v & 3) << 3;
                gp = W + (size_t)(bn + r) * K + k0 + seg;
                sa = sb + (uint32_t)(5120 + r * SM_STRIDE + seg) * 2;
            }
            asm volatile("cp.async.cg.shared.global [%0], [%1], 16, %2;"
                         :: "r"(sa), "l"(gp), "r"(sz));
        }
        asm volatile("cp.async.commit_group;" ::: "memory");
    };

    auto compute_ks = [&](uint32_t st, int ks) {
        uint32_t ah[2][4], al[2][4], bb[4][4];
        #pragma unroll
        for (int bt = 0; bt < 4; bt++) {
            uint32_t off = (uint32_t)(5120 + (b_row + bt * 16) * SM_STRIDE + ks * 16 + b_kc) * 2;
            ldm4(bb[bt], st + off);
        }
        #pragma unroll
        for (int mt = 0; mt < 2; mt++) {
            uint32_t o2 = (uint32_t)((a_row + mt * 16) * SM_STRIDE + ks * 16 + a_kc) * 2;
            ldm4(ah[mt], st + o2);
            ldm4(al[mt], st + 2560 * 2 + o2);
        }
        #pragma unroll
        for (int mt = 0; mt < 2; mt++)
            #pragma unroll
            for (int nt = 0; nt < 8; nt++)
                mma_hf(acc[mt][nt], ah[mt], bb[nt >> 1][(nt & 1) * 2], bb[nt >> 1][(nt & 1) * 2 + 1]);
        #pragma unroll
        for (int mt = 0; mt < 2; mt++)
            #pragma unroll
            for (int nt = 0; nt < 8; nt++)
                mma_hf(acc[mt][nt], al[mt], bb[nt >> 1][(nt & 1) * 2], bb[nt >> 1][(nt & 1) * 2 + 1]);
    };

    issue(0);
    for (int c = 0; c < NC; c++) {
        asm volatile("cp.async.wait_group 0;" ::: "memory");
        __syncthreads();
        const uint32_t st = sbase + (uint32_t)(c & 1) * (STAGE_ELE * 2);
        compute_ks(st, 0);
        if (c + 1 < NC) issue(c + 1);
        compute_ks(st, 1);
        __syncthreads();
    }

    #pragma unroll
    for (int mt = 0; mt < 2; mt++) {
        int rb = bm + warpM * 32 + mt * 16 + (lane >> 2);
        #pragma unroll
        for (int half = 0; half < 2; half++) {
            int rr = rb + half * 8;
            if (rr >= M) continue;
            #pragma unroll
            for (int nt = 0; nt < 8; nt++) {
                int col = bn + warpN * 64 + nt * 8 + ((lane & 3) << 1);
                size_t o = (size_t)rr * Nn + col;
                if (nsplit > 1) {
                    *(float2*)(part + (size_t)kz * ((size_t)T_TOT * Nn) + o) =
                        make_float2(acc[mt][nt][half * 2 + 0], acc[mt][nt][half * 2 + 1]);
                    continue;
                }
                float v0 = acc[mt][nt][half * 2 + 0] + bias[col];
                float v1 = acc[mt][nt][half * 2 + 1] + bias[col + 1];
                if (act) { v0 = v0 * normcdff(v0); v1 = v1 * normcdff(v1); }
                if (Ch) {
                    __half h0 = __float2half_rn(v0), h1 = __float2half_rn(v1);
                    *(uint32_t*)(Ch + o) = (uint32_t)__half_as_ushort(h0) | ((uint32_t)__half_as_ushort(h1) << 16);
                    *(uint32_t*)(Cl + o) = pack_hf2(v0 - __half2float(h0), v1 - __half2float(h1));
                } else {
                    *(float2*)(Cf + o) = make_float2(v0, v1);
                }
            }
        }
    }
}

// ---------------- QKV post: combine 3 partials + bias, RMS norm + RoPE ----------------
__global__ void qkvpost_kernel(const float* __restrict__ part, const float* __restrict__ qb,
                               const float* __restrict__ qn, const float* __restrict__ kn,
                               const float* __restrict__ rc, const float* __restrict__ rs,
                               __half* __restrict__ Qh, __half* __restrict__ Ql,
                               __half* __restrict__ Kh, __half* __restrict__ Vh,
                               int posmod)
{
    int gw = (blockIdx.x * blockDim.x + threadIdx.x) >> 5;
    int lane = threadIdx.x & 31;
    int t = gw / NHEAD, h = gw - (gw / NHEAD) * NHEAD;
    if (t >= T_TOT) return;
    const float* r0 = part + (size_t)t * 2304 + h * 64;
    const float* r1 = r0 + QKV_PART_STRIDE;
    const float* r2 = r1 + QKV_PART_STRIDE;
    const float* bb = qb + h * 64;
    float q0 = r0[lane] + r1[lane] + r2[lane] + bb[lane];
    float q1 = r0[lane + 32] + r1[lane + 32] + r2[lane + 32] + bb[lane + 32];
    float k0 = r0[768 + lane] + r1[768 + lane] + r2[768 + lane] + qb[768 + h * 64 + lane];
    float k1 = r0[768 + lane + 32] + r1[768 + lane + 32] + r2[768 + lane + 32] + qb[768 + h * 64 + lane + 32];
    float v0 = r0[1536 + lane] + r1[1536 + lane] + r2[1536 + lane] + qb[1536 + h * 64 + lane];
    float v1 = r0[1536 + lane + 32] + r1[1536 + lane + 32] + r2[1536 + lane + 32] + qb[1536 + h * 64 + lane + 32];
    float sq = q0 * q0 + q1 * q1, sk = k0 * k0 + k1 * k1;
    #pragma unroll
    for (int off = 16; off; off >>= 1) {
        sq += __shfl_xor_sync(0xffffffffu, sq, off);
        sk += __shfl_xor_sync(0xffffffffu, sk, off);
    }
    float rq = rsqrtf(sq * (1.f / 64.f) + 1e-6f);
    float rk = rsqrtf(sk * (1.f / 64.f) + 1e-6f);
    q0 *= rq * qn[lane]; q1 *= rq * qn[lane + 32];
    k0 *= rk * kn[lane]; k1 *= rk * kn[lane + 32];
    int pos = t % posmod;
    const float* cr = rc + (size_t)pos * 64;
    const float* sr = rs + (size_t)pos * 64;
    float c0 = cr[lane], c1 = cr[lane + 32];
    float s0 = sr[lane], s1 = sr[lane + 32];
    float sgn = (lane < 16) ? -1.f : 1.f;
    float qp0 = __shfl_xor_sync(0xffffffffu, q0, 16);
    float qp1 = __shfl_xor_sync(0xffffffffu, q1, 16);
    float kp0 = __shfl_xor_sync(0xffffffffu, k0, 16);
    float kp1 = __shfl_xor_sync(0xffffffffu, k1, 16);
    float qo0 = (q0 * c0 + sgn * qp0 * s0) * 0.125f;
    float qo1 = (q1 * c1 + sgn * qp1 * s1) * 0.125f;
    float ko0 = k0 * c0 + sgn * kp0 * s0;
    float ko1 = k1 * c1 + sgn * kp1 * s1;
    size_t base = ((size_t)h * T_TOT + t) * 64;
    __half hh;
    hh = __float2half_rn(qo0); Qh[base + lane] = hh;      Ql[base + lane]      = __float2half_rn(qo0 - __half2float(hh));
    hh = __float2half_rn(qo1); Qh[base + 32 + lane] = hh; Ql[base + 32 + lane] = __float2half_rn(qo1 - __half2float(hh));
    Kh[base + lane]      = __float2half_rn(ko0);
    Kh[base + 32 + lane] = __float2half_rn(ko1);
    Vh[base + lane]      = __float2half_rn(v0);
    Vh[base + 32 + lane] = __float2half_rn(v1);
}

// ---------------- fp16 tensor-core flash attention ----------------
#define ATT_STRIDE 72
#define A_QH 0
#define A_QL 4608
#define A_STG 9216
#define A_STG_ELE 9216
#define ATT_SMEM (27648 * 2)

__global__ __launch_bounds__(128) void attn_mma(
    const __half* __restrict__ Qh, const __half* __restrict__ Ql,
    const __half* __restrict__ Kh, const __half* __restrict__ Vh,
    const float* __restrict__ kvmask,
    __half* __restrict__ Oh, __half* __restrict__ Ol, int nq)
{
    extern __shared__ __align__(16) uint16_t smA[];
    const int tid = threadIdx.x, wid = tid >> 5, lane = tid & 31;
    const int qt = blockIdx.x, h = blockIdx.y, z = blockIdx.z;
    const int t0 = z * nq;
    const size_t hb = (size_t)h * T_TOT * 64;
    const uint32_t sbase = smem_u32(smA);
    const float* kvrow = kvmask + (size_t)z * nq;

    for (int i = tid; i < 512; i += 128) {
        int r = i >> 3, sg = i & 7;
        int qrow = qt * 64 + r;
        uint4 vh = make_uint4(0, 0, 0, 0), vl = make_uint4(0, 0, 0, 0);
        if (qrow < nq) {
            size_t go = hb + (size_t)(t0 + qrow) * 64 + sg * 8;
            vh = *(const uint4*)(Qh + go);
            vl = *(const uint4*)(Ql + go);
        }
        *(uint4*)((char*)smA + (A_QH + r * ATT_STRIDE + sg * 8) * 2) = vh;
        *(uint4*)((char*)smA + (A_QL + r * ATT_STRIDE + sg * 8) * 2) = vl;
    }
    __syncthreads();

    uint32_t qhf[4][4], qlf[4][4];
    {
        int arow = wid * 16 + (lane & 15);
        int akc = (lane >> 4) * 8;
        #pragma unroll
        for (int kc = 0; kc < 4; kc++) {
            uint32_t off = (uint32_t)(arow * ATT_STRIDE + kc * 16 + akc) * 2;
            ldm4(qhf[kc], sbase + A_QH * 2 + off);
            ldm4(qlf[kc], sbase + A_QL * 2 + off);
        }
    }

    auto stage_load = [&](int kt) {
        int s = kt & 1;
        uint32_t sb = sbase + (uint32_t)(A_STG + s * A_STG_ELE) * 2;
        int kbase = kt * 64;
        #pragma unroll
        for (int it = 0; it < 8; it++) {
            int i = tid + it * 128;
            int m = i >> 9, v = i & 511, r = v >> 3, sg = v & 7;
            int key = kbase + r;
            int sz = 16;
            if (key >= nq) { sz = 0; key = nq - 1; }
            const __half* gp = (m == 0 ? Kh : Vh) + hb + (size_t)(t0 + key) * 64 + sg * 8;
            uint32_t da = sb + (uint32_t)(m * 4608 + r * ATT_STRIDE + sg * 8) * 2;
            asm volatile("cp.async.cg.shared.global [%0], [%1], 16, %2;"
                         :: "r"(da), "l"(gp), "r"(sz));
        }
        asm volatile("cp.async.commit_group;" ::: "memory");
    };

    float o[8][4];
    #pragma unroll
    for (int i = 0; i < 8; i++)
        #pragma unroll
        for (int j = 0; j < 4; j++) o[i][j] = 0.f;
    float m0 = -1e30f, m1 = -1e30f, l0 = 0.f, l1 = 0.f;

    const int nkt = (nq + 63) >> 6;
    const int brow = ((lane >> 4) & 1) * 8 + (lane & 7);
    const int bkc = ((lane >> 3) & 1) * 8;
    const int vr0 = ((lane >> 3) & 1) * 8 + (lane & 7);
    const int vc0 = (lane >> 4) * 8;

    stage_load(0);
    for (int kt = 0; kt < nkt; kt++) {
        if (kt + 1 < nkt) {
            stage_load(kt + 1);
            asm volatile("cp.async.wait_group 1;" ::: "memory");
        } else {
            asm volatile("cp.async.wait_group 0;" ::: "memory");
        }
        __syncthreads();
        uint32_t sb = sbase + (uint32_t)(A_STG + (kt & 1) * A_STG_ELE) * 2;
        int kbase = kt * 64;

        float s_[8][4];
        #pragma unroll
        for (int nt = 0; nt < 8; nt++) {
            int key = kbase + nt * 8 + ((lane & 3) << 1);
            float b0 = (key < nq) ? (1.f - kvrow[key]) * -10000.f : -1e30f;
            float b1 = (key + 1 < nq) ? (1.f - kvrow[key + 1]) * -10000.f : -1e30f;
            s_[nt][0] = b0; s_[nt][1] = b1; s_[nt][2] = b0; s_[nt][3] = b1;
        }
        #pragma unroll
        for (int np = 0; np < 4; np++) {
            #pragma unroll
            for (int kc = 0; kc < 4; kc++) {
                uint32_t off = (uint32_t)((np * 16 + brow) * ATT_STRIDE + kc * 16 + bkc) * 2;
                uint32_t kh4[4];
                ldm4(kh4, sb + off);
                mma_hf(s_[2 * np],     qhf[kc], kh4[0], kh4[1]);
                mma_hf(s_[2 * np + 1], qhf[kc], kh4[2], kh4[3]);
                mma_hf(s_[2 * np],     qlf[kc], kh4[0], kh4[1]);
                mma_hf(s_[2 * np + 1], qlf[kc], kh4[2], kh4[3]);
            }
        }
        float mx0 = -1e30f, mx1 = -1e30f;
        #pragma unroll
        for (int nt = 0; nt < 8; nt++) {
            mx0 = fmaxf(mx0, fmaxf(s_[nt][0], s_[nt][1]));
            mx1 = fmaxf(mx1, fmaxf(s_[nt][2], s_[nt][3]));
        }
        mx0 = fmaxf(mx0, __shfl_xor_sync(0xffffffffu, mx0, 1));
        mx0 = fmaxf(mx0, __shfl_xor_sync(0xffffffffu, mx0, 2));
        mx1 = fmaxf(mx1, __shfl_xor_sync(0xffffffffu, mx1, 1));
        mx1 = fmaxf(mx1, __shfl_xor_sync(0xffffffffu, mx1, 2));
        float mn0 = fmaxf(m0, mx0), mn1 = fmaxf(m1, mx1);
        float sc0 = __expf(m0 - mn0), sc1 = __expf(m1 - mn1);
        m0 = mn0; m1 = mn1;
        float ps0 = 0.f, ps1 = 0.f;
        #pragma unroll
        for (int nt = 0; nt < 8; nt++) {
            s_[nt][0] = __expf(s_[nt][0] - mn0); ps0 += s_[nt][0];
            s_[nt][1] = __expf(s_[nt][1] - mn0); ps0 += s_[nt][1];
            s_[nt][2] = __expf(s_[nt][2] - mn1); ps1 += s_[nt][2];
            s_[nt][3] = __expf(s_[nt][3] - mn1); ps1 += s_[nt][3];
        }
        ps0 += __shfl_xor_sync(0xffffffffu, ps0, 1);
        ps0 += __shfl_xor_sync(0xffffffffu, ps0, 2);
        ps1 += __shfl_xor_sync(0xffffffffu, ps1, 1);
        ps1 += __shfl_xor_sync(0xffffffffu, ps1, 2);
        l0 = l0 * sc0 + ps0;
        l1 = l1 * sc1 + ps1;
        #pragma unroll
        for (int nt = 0; nt < 8; nt++) {
            o[nt][0] *= sc0; o[nt][1] *= sc0; o[nt][2] *= sc1; o[nt][3] *= sc1;
        }
        uint32_t pfh[4][4], pfl[4][4];
        #pragma unroll
        for (int kc = 0; kc < 4; kc++) {
            #pragma unroll
            for (int q = 0; q < 4; q++) {
                float a = s_[2 * kc + (q >> 1)][(q & 1) * 2];
                float b = s_[2 * kc + (q >> 1)][(q & 1) * 2 + 1];
                __half ha = __float2half_rn(a), hb2 = __float2half_rn(b);
                pfh[kc][q] = (uint32_t)__half_as_ushort(ha) | ((uint32_t)__half_as_ushort(hb2) << 16);
                pfl[kc][q] = pack_hf2(a - __half2float(ha), b - __half2float(hb2));
            }
        }
        #pragma unroll
        for (int kc = 0; kc < 4; kc++) {
            #pragma unroll
            for (int dp = 0; dp < 4; dp++) {
                uint32_t off = (uint32_t)((kc * 16 + vr0) * ATT_STRIDE + dp * 16 + vc0) * 2;
                uint32_t vh4[4];
                ldm4t(vh4, sb + 4608 * 2 + off);
                mma_hf(o[2 * dp],     pfh[kc], vh4[0], vh4[1]);
                mma_hf(o[2 * dp + 1], pfh[kc], vh4[2], vh4[3]);
                mma_hf(o[2 * dp],     pfl[kc], vh4[0], vh4[1]);
                mma_hf(o[2 * dp + 1], pfl[kc], vh4[2], vh4[3]);
            }
        }
        __syncthreads();
    }

    float inv0 = 1.f / l0, inv1 = 1.f / l1;
    int r = lane >> 2;
    int q0row = qt * 64 + wid * 16 + r;
    int q1row = q0row + 8;
    #pragma unroll
    for (int nt = 0; nt < 8; nt++) {
        int d = nt * 8 + ((lane & 3) << 1);
        if (q0row < nq) {
            float a = o[nt][0] * inv0, b = o[nt][1] * inv0;
            size_t ob = (size_t)(t0 + q0row) * C_DIM + h * 64 + d;
            __half ha = __float2half_rn(a), hb2 = __float2half_rn(b);
            *(uint32_t*)(Oh + ob) = (uint32_t)__half_as_ushort(ha) | ((uint32_t)__half_as_ushort(hb2) << 16);
            *(uint32_t*)(Ol + ob) = pack_hf2(a - __half2float(ha), b - __half2float(hb2));
        }
        if (q1row < nq) {
            float a = o[nt][2] * inv1, b = o[nt][3] * inv1;
            size_t ob = (size_t)(t0 + q1row) * C_DIM + h * 64 + d;
            __half ha = __float2half_rn(a), hb2 = __float2half_rn(b);
            *(uint32_t*)(Oh + ob) = (uint32_t)__half_as_ushort(ha) | ((uint32_t)__half_as_ushort(hb2) << 16);
            *(uint32_t*)(Ol + ob) = pack_hf2(a - __half2float(ha), b - __half2float(hb2));
        }
    }
}

// ---------------- emit output ----------------
__global__ __launch_bounds__(256) void emit_kernel(const float* __restrict__ xloc, const float* __restrict__ xg,
                                                   const float* __restrict__ fw, const float* __restrict__ fb,
                                                   float* __restrict__ out)
{
    __shared__ float sh[8];
    int row = blockIdx.x;
    int s = row / 576, n = row - s * 576 + 1;
    int t = s * 577 + n;
    int tid = threadIdx.x;
    const float* xr = xg + (size_t)t * C_DIM;
    float v0 = xr[tid], v1 = xr[tid + 256], v2 = xr[tid + 512];
    float mean = block_sum_256(v0 + v1 + v2, sh) * (1.f / 768.f);
    float d0 = v0 - mean, d1 = v1 - mean, d2 = v2 - mean;
    float var = block_sum_256(d0 * d0 + d1 * d1 + d2 * d2, sh) * (1.f / 768.f);
    float rstd = rsqrtf(var + 1e-6f);
    const float* lr = xloc + (size_t)t * C_DIM;
    float* orow = out + (size_t)row * 1536;
    orow[tid]       = lr[tid];
    orow[tid + 256] = lr[tid + 256];
    orow[tid + 512] = lr[tid + 512];
    orow[768 + tid]       = d0 * rstd * fw[tid]       + fb[tid];
    orow[768 + tid + 256] = d1 * rstd * fw[tid + 256] + fb[tid + 256];
    orow[768 + tid + 512] = d2 * rstd * fw[tid + 512] + fb[tid + 512];
}

__global__ void cam_kernel(const float* __restrict__ xloc, const float* __restrict__ xg,
                           float* __restrict__ out) {
    int s = blockIdx.x;
    int t = s * 577;
    for (int c = threadIdx.x; c < C_DIM; c += 256) {
        out[s * 1536 + c]       = xloc[(size_t)t * C_DIM + c];
        out[s * 1536 + 768 + c] = xg[(size_t)t * C_DIM + c];
    }
}

// ---------------- host orchestration ----------------
extern "C" void kernel_launch(void* const* d_in, const int* in_sizes, int n_in,
                              void* d_out, int out_size)
{
    const float* x_in  = (const float*)d_in[0];
    const float* rc_l  = (const float*)d_in[1];
    const float* rs_l  = (const float*)d_in[2];
    const float* rc_g  = (const float*)d_in[3];
    const float* rs_g  = (const float*)d_in[4];
    const float* kv_l  = (const float*)d_in[5];
    const float* kv_g  = (const float*)d_in[6];
    const float* cam   = (const float*)d_in[7];
    const float* qkv_w = (const float*)d_in[8];
    const float* qkv_b = (const float*)d_in[9];
    const float* qn_w  = (const float*)d_in[10];
    const float* kn_w  = (const float*)d_in[11];
    const float* pw    = (const float*)d_in[12];
    const float* pb    = (const float*)d_in[13];
    const float* g1    = (const float*)d_in[14];
    const float* g2    = (const float*)d_in[15];
    const float* n1w   = (const float*)d_in[16];
    const float* n1b   = (const float*)d_in[17];
    const float* n2w   = (const float*)d_in[18];
    const float* n2b   = (const float*)d_in[19];
    const float* f1w   = (const float*)d_in[20];
    const float* f1b   = (const float*)d_in[21];
    const float* f2w   = (const float*)d_in[22];
    const float* f2b   = (const float*)d_in[23];
    const float* fnw   = (const float*)d_in[24];
    const float* fnb   = (const float*)d_in[25];
    float* out = (float*)d_out;

    float *p_x, *p_loc, *p_part;
    __half *p_w, *p_sh, *p_sl, *p_mh, *p_ml, *p_qh, *p_ql, *p_kh, *p_vh;
    cudaGetSymbolAddress((void**)&p_x,   g_x);
    cudaGetSymbolAddress((void**)&p_loc, g_loc);
    cudaGetSymbolAddress((void**)&p_part, g_part);
    cudaGetSymbolAddress((void**)&p_w,   g_w);
    cudaGetSymbolAddress((void**)&p_sh,  g_sh);
    cudaGetSymbolAddress((void**)&p_sl,  g_sl);
    cudaGetSymbolAddress((void**)&p_mh,  g_mh);
    cudaGetSymbolAddress((void**)&p_ml,  g_ml);
    cudaGetSymbolAddress((void**)&p_qh,  g_qh);
    cudaGetSymbolAddress((void**)&p_ql,  g_ql);
    cudaGetSymbolAddress((void**)&p_kh,  g_kh);
    cudaGetSymbolAddress((void**)&p_vh,  g_vh);

    cudaFuncSetAttribute(gemm_mma, cudaFuncAttributeMaxDynamicSharedMemorySize, GEMM_SMEM);
    cudaFuncSetAttribute(attn_mma, cudaFuncAttributeMaxDynamicSharedMemorySize, ATT_SMEM);

    const int eb = (NE + 255) / 256;
    convall_kernel<<<(W_TOTAL / 4 + 255) / 256, 256>>>(qkv_w, pw, f1w, f2w, p_w);
    init_x_kernel<<<eb, 256>>>(x_in, cam);

    const int MT = (T_TOT + 63) / 64;   // 19 M-tiles
    int outidx = 0;
    for (int i = 0; i < 12; i++) {
        bool isg = (i & 1);
        int nb = isg ? 1 : 2;
        int nq = isg ? 1154 : 577;
        const float* rc = isg ? rc_g : rc_l;
        const float* rs = isg ? rs_g : rs_l;
        const float* kv = isg ? kv_g : kv_l;

        if (i == 0)
            ln_kernel<<<T_TOT, 256>>>(p_x, p_sh, p_sl, n1w, n1b);
        // QKV: split-K=3 (1026 CTAs x 8 chunks)
        gemm_mma<<<dim3(18, MT, 3), 128, GEMM_SMEM>>>(
            p_sh, p_sl, p_w + W_QKV_OFF + (size_t)i * 2304 * 768,
            nullptr, nullptr, nullptr, nullptr, p_part, T_TOT, 2304, 768, 0, 3);
        qkvpost_kernel<<<(T_TOT * NHEAD * 32 + 127) / 128, 128>>>(
            p_part, qkv_b + i * 2304, qn_w + i * 64, kn_w + i * 64, rc, rs,
            p_qh, p_ql, p_kh, p_vh, nq);
        attn_mma<<<dim3((nq + 63) / 64, NHEAD, nb), 128, ATT_SMEM>>>(
            p_qh, p_ql, p_kh, p_vh, kv, p_sh, p_sl, nq);
        // proj: split-K=6 (684 CTAs x 4 chunks)
        gemm_mma<<<dim3(6, MT, 6), 128, GEMM_SMEM>>>(
            p_sh, p_sl, p_w + W_PROJ_OFF + (size_t)i * 768 * 768,
            nullptr, nullptr, nullptr, nullptr, p_part, T_TOT, 768, 768, 0, 6);
        combine_ln_kernel<<<T_TOT, 256>>>(p_x, p_part, pb + i * 768, g1 + i * 768, 6,
                                          n2w + i * 768, n2b + i * 768, p_sh, p_sl, nullptr);
        gemm_mma<<<dim3(24, MT, 1), 128, GEMM_SMEM>>>(
            p_sh, p_sl, p_w + W_FC1_OFF + (size_t)i * 3072 * 768,
            f1b + i * 3072, nullptr, p_mh, p_ml, nullptr, T_TOT, 3072, 768, 1, 1);
        // fc2: split-K=6 (684 CTAs x 16 chunks)
        gemm_mma<<<dim3(6, MT, 6), 128, GEMM_SMEM>>>(
            p_mh, p_ml, p_w + W_FC2_OFF + (size_t)i * 768 * 3072,
            nullptr, nullptr, nullptr, nullptr, p_part, T_TOT, 768, 3072, 0, 6);
        if (i < 11) {
            float* locp = (i == 4 || i == 10) ? p_loc : nullptr;
            combine_ln_kernel<<<T_TOT, 256>>>(p_x, p_part, f2b + i * 768, g2 + i * 768, 6,
                                              n1w + (i + 1) * 768, n1b + (i + 1) * 768, p_sh, p_sl, locp);
        } else {
            combine_kernel<<<eb, 256>>>(p_x, p_part, f2b + i * 768, g2 + i * 768, 6);
        }

        if (i == 2 || i == 5 || i == 8 || i == 11) {
            const float* loc = (i == 5 || i == 11) ? p_loc : p_x;
            emit_kernel<<<1152, 256>>>(loc, p_x, fnw, fnb, out + (size_t)outidx * 1769472);
            if (i == 11) cam_kernel<<<2, 256>>>(loc, p_x, out + 4ull * 1769472);
            outidx++;
        }
    }
}

// round 16
// speedup vs baseline: 1.0698x; 1.0698x over previous
#include <cuda_runtime.h>
#include <cuda_fp16.h>
#include <math.h>
#include <stdint.h>

#define T_TOT 1154
#define C_DIM 768
#define NHEAD 12
#define NE (T_TOT * C_DIM)
#define QKV_PART_STRIDE 2658816     // 1154*2304

// weight offsets (elements)
#define W_QKV_OFF 0
#define W_PROJ_OFF 21233664
#define W_FC1_OFF  28311552
#define W_FC2_OFF  56623104
#define W_TOTAL    84934656

// ---------------- device scratch ----------------
__device__ float g_x[NE];
__device__ float g_loc[NE];
__device__ float g_part[3 * QKV_PART_STRIDE];
__device__ __half g_w[W_TOTAL];
__device__ __half g_sh[NE];
__device__ __half g_sl[NE];
__device__ __half g_mh[NE * 4];
__device__ __half g_qh[NHEAD * T_TOT * 64];
__device__ __half g_ql[NHEAD * T_TOT * 64];
__device__ __half g_kh[NHEAD * T_TOT * 64];
__device__ __half g_vh[NHEAD * T_TOT * 64];

// ---------------- helpers ----------------
__device__ __forceinline__ float block_sum_256(float v, float* sh) {
    #pragma unroll
    for (int off = 16; off; off >>= 1) v += __shfl_xor_sync(0xffffffffu, v, off);
    __syncthreads();
    if ((threadIdx.x & 31) == 0) sh[threadIdx.x >> 5] = v;
    __syncthreads();
    float r = 0.f;
    #pragma unroll
    for (int i = 0; i < 8; i++) r += sh[i];
    return r;
}

__device__ __forceinline__ uint32_t smem_u32(const void* p) {
    uint32_t a;
    asm("{ .reg .u64 t; cvta.to.shared.u64 t, %1; cvt.u32.u64 %0, t; }" : "=r"(a) : "l"(p));
    return a;
}

__device__ __forceinline__ void ldm4(uint32_t* r, uint32_t addr) {
    asm volatile("ldmatrix.sync.aligned.m8n8.x4.shared.b16 {%0,%1,%2,%3}, [%4];"
                 : "=r"(r[0]), "=r"(r[1]), "=r"(r[2]), "=r"(r[3]) : "r"(addr));
}

__device__ __forceinline__ void ldm4t(uint32_t* r, uint32_t addr) {
    asm volatile("ldmatrix.sync.aligned.m8n8.x4.trans.shared.b16 {%0,%1,%2,%3}, [%4];"
                 : "=r"(r[0]), "=r"(r[1]), "=r"(r[2]), "=r"(r[3]) : "r"(addr));
}

__device__ __forceinline__ void mma_hf(float* d, const uint32_t* a, uint32_t b0, uint32_t b1) {
    asm volatile(
        "mma.sync.aligned.m16n8k16.row.col.f32.f16.f16.f32 "
        "{%0,%1,%2,%3}, {%4,%5,%6,%7}, {%8,%9}, {%0,%1,%2,%3};"
        : "+f"(d[0]), "+f"(d[1]), "+f"(d[2]), "+f"(d[3])
        : "r"(a[0]), "r"(a[1]), "r"(a[2]), "r"(a[3]), "r"(b0), "r"(b1));
}

__device__ __forceinline__ uint32_t pack_hf2(float a, float b) {
    __half ha = __float2half_rn(a), hb = __float2half_rn(b);
    return (uint32_t)__half_as_ushort(ha) | ((uint32_t)__half_as_ushort(hb) << 16);
}

// ---------------- weight conversion ----------------
__global__ void convall_kernel(const float* __restrict__ qkv_w, const float* __restrict__ pw,
                               const float* __restrict__ f1w, const float* __restrict__ f2w,
                               __half* __restrict__ dw) {
    int i = blockIdx.x * 256 + threadIdx.x;
    if (i >= W_TOTAL / 4) return;
    const float* src;
    int local;
    if (i < W_PROJ_OFF / 4)      { src = qkv_w; local = i; }
    else if (i < W_FC1_OFF / 4)  { src = pw;    local = i - W_PROJ_OFF / 4; }
    else if (i < W_FC2_OFF / 4)  { src = f1w;   local = i - W_FC1_OFF / 4; }
    else                         { src = f2w;   local = i - W_FC2_OFF / 4; }
    float4 x = ((const float4*)src)[local];
    uint2 hv;
    hv.x = pack_hf2(x.x, x.y);
    hv.y = pack_hf2(x.z, x.w);
    ((uint2*)dw)[i] = hv;
}

// ---------------- init ----------------
__global__ void init_x_kernel(const float* __restrict__ xin, const float* __restrict__ cam) {
    int i = blockIdx.x * 256 + threadIdx.x;
    if (i >= NE) return;
    int t = i / C_DIM, c = i - t * C_DIM;
    float v;
    if (t == 0) v = cam[c];
    else if (t == 577) v = cam[C_DIM + c];
    else v = xin[i];
    g_x[i] = v;
}

// ---------------- LayerNorm (layer 0 only): split fp16 out (QKV is 2-term) ----------------
__global__ __launch_bounds__(256) void ln_kernel(const float* __restrict__ x,
                                                 __half* __restrict__ yh, __half* __restrict__ yl,
                                                 const float* __restrict__ w, const float* __restrict__ b) {
    __shared__ float sh[8];
    int t = blockIdx.x, tid = threadIdx.x;
    const float* xr = x + (size_t)t * C_DIM;
    float v0 = xr[tid], v1 = xr[tid + 256], v2 = xr[tid + 512];
    float mean = block_sum_256(v0 + v1 + v2, sh) * (1.f / 768.f);
    float d0 = v0 - mean, d1 = v1 - mean, d2 = v2 - mean;
    float var = block_sum_256(d0 * d0 + d1 * d1 + d2 * d2, sh) * (1.f / 768.f);
    float rstd = rsqrtf(var + 1e-6f);
    float o0 = d0 * rstd * w[tid]       + b[tid];
    float o1 = d1 * rstd * w[tid + 256] + b[tid + 256];
    float o2 = d2 * rstd * w[tid + 512] + b[tid + 512];
    size_t base = (size_t)t * C_DIM + tid;
    __half h0 = __float2half_rn(o0);
    __half h1 = __float2half_rn(o1);
    __half h2 = __float2half_rn(o2);
    yh[base] = h0;       if (yl) yl[base]       = __float2half_rn(o0 - __half2float(h0));
    yh[base + 256] = h1; if (yl) yl[base + 256] = __float2half_rn(o1 - __half2float(h1));
    yh[base + 512] = h2; if (yl) yl[base + 512] = __float2half_rn(o2 - __half2float(h2));
}

// ---------------- fused combine + residual + LN (sums ns partials) ----------------
__global__ __launch_bounds__(256) void combine_ln_kernel(
    float* __restrict__ x, const float* __restrict__ part,
    const float* __restrict__ bias, const float* __restrict__ gamma, int ns,
    const float* __restrict__ w, const float* __restrict__ b,
    __half* __restrict__ yh, __half* __restrict__ yl,
    float* __restrict__ loc)
{
    __shared__ float sh[8];
    int t = blockIdx.x, tid = threadIdx.x;
    float v[3];
    #pragma unroll
    for (int j = 0; j < 3; j++) {
        int c = tid + j * 256;
        size_t idx = (size_t)t * C_DIM + c;
        float s = part[idx];
        for (int p = 1; p < ns; p++) s += part[(size_t)p * NE + idx];
        float xv = x[idx] + gamma[c] * (s + bias[c]);
        x[idx] = xv;
        if (loc) loc[idx] = xv;
        v[j] = xv;
    }
    float mean = block_sum_256(v[0] + v[1] + v[2], sh) * (1.f / 768.f);
    float d0 = v[0] - mean, d1 = v[1] - mean, d2 = v[2] - mean;
    float var = block_sum_256(d0 * d0 + d1 * d1 + d2 * d2, sh) * (1.f / 768.f);
    float rstd = rsqrtf(var + 1e-6f);
    float o0 = d0 * rstd * w[tid]       + b[tid];
    float o1 = d1 * rstd * w[tid + 256] + b[tid + 256];
    float o2 = d2 * rstd * w[tid + 512] + b[tid + 512];
    size_t base = (size_t)t * C_DIM + tid;
    __half h0 = __float2half_rn(o0);
    __half h1 = __float2half_rn(o1);
    __half h2 = __float2half_rn(o2);
    yh[base] = h0;       if (yl) yl[base]       = __float2half_rn(o0 - __half2float(h0));
    yh[base + 256] = h1; if (yl) yl[base + 256] = __float2half_rn(o1 - __half2float(h1));
    yh[base + 512] = h2; if (yl) yl[base + 512] = __float2half_rn(o2 - __half2float(h2));
}

// ---------------- plain combine (layer 11 fc2) ----------------
__global__ void combine_kernel(float* __restrict__ x, const float* __restrict__ part,
                               const float* __restrict__ bias, const float* __restrict__ gamma,
                               int ns) {
    int i = blockIdx.x * 256 + threadIdx.x;
    if (i >= NE) return;
    int c = i % C_DIM;
    float s = part[i];
    for (int p = 1; p < ns; p++) s += part[(size_t)p * NE + i];
    x[i] += gamma[c] * (s + bias[c]);
}

// ---------------- fp16 GEMM: CTA 128 thr, tile 64x128, 2-stage, 4 CTAs/SM ----------------
// Al != nullptr -> 2-term activation split (QKV); else 1-term (proj/fc1/fc2).
#define SM_STRIDE 40
#define STAGE_ELE 10240
#define GEMM_SMEM 40960

__global__ __launch_bounds__(128, 4) void gemm_mma(
    const __half* __restrict__ Ah, const __half* __restrict__ Al,
    const __half* __restrict__ W,
    const float* __restrict__ bias,
    float* __restrict__ Cf, __half* __restrict__ Ch, __half* __restrict__ Cl,
    float* __restrict__ part,
    int M, int Nn, int K, int act, int nsplit)
{
    extern __shared__ __align__(16) uint16_t sm[];
    const int tid = threadIdx.x;
    const int wid = tid >> 5, lane = tid & 31;
    const int warpM = wid >> 1, warpN = wid & 1;
    const int bm = blockIdx.y * 64, bn = blockIdx.x * 128;
    const int kz = blockIdx.z;
    const int Kp = K / nsplit;
    const int kz0 = kz * Kp;
    const uint32_t sbase = smem_u32(sm);
    const int aU = Al ? 512 : 256;        // A 16B-units per stage

    float acc[2][8][4];
    #pragma unroll
    for (int i = 0; i < 2; i++)
        #pragma unroll
        for (int j = 0; j < 8; j++)
            #pragma unroll
            for (int k = 0; k < 4; k++) acc[i][j][k] = 0.f;

    const int a_row = warpM * 32 + (lane & 15);
    const int a_kc  = (lane >> 4) * 8;
    const int b_row = warpN * 64 + ((lane >> 4) & 1) * 8 + (lane & 7);
    const int b_kc  = ((lane >> 3) & 1) * 8;

    const int NC = Kp >> 5;

    auto issue = [&](int c) {
        const int s = c & 1, k0 = kz0 + (c << 5);
        const uint32_t sb = sbase + (uint32_t)s * (STAGE_ELE * 2);
        const int total = aU + 512;
        for (int u = tid; u < total; u += 128) {
            const __half* gp;
            uint32_t sa;
            int sz = 16;
            if (u < aU) {
                int mat = u >> 8;                 // 0 (hi) or 1 (lo, only when aU=512)
                int v = u & 255;
                int r = v >> 2, seg = (v & 3) << 3;
                int gr = bm + r;
                if (gr >= M) { sz = 0; gr = M - 1; }
                gp = (mat == 0 ? Ah : Al) + (size_t)gr * K + k0 + seg;
                sa = sb + (uint32_t)(mat * 2560 + r * SM_STRIDE + seg) * 2;
            } else {
                int v = u - aU;
                int r = v >> 2, seg = (v & 3) << 3;
                gp = W + (size_t)(bn + r) * K + k0 + seg;
                sa = sb + (uint32_t)(5120 + r * SM_STRIDE + seg) * 2;
            }
            asm volatile("cp.async.cg.shared.global [%0], [%1], 16, %2;"
                         :: "r"(sa), "l"(gp), "r"(sz));
        }
        asm volatile("cp.async.commit_group;" ::: "memory");
    };

    auto compute_ks = [&](uint32_t st, int ks) {
        uint32_t ah[2][4], bb[4][4];
        #pragma unroll
        for (int bt = 0; bt < 4; bt++) {
            uint32_t off = (uint32_t)(5120 + (b_row + bt * 16) * SM_STRIDE + ks * 16 + b_kc) * 2;
            ldm4(bb[bt], st + off);
        }
        #pragma unroll
        for (int mt = 0; mt < 2; mt++) {
            uint32_t o2 = (uint32_t)((a_row + mt * 16) * SM_STRIDE + ks * 16 + a_kc) * 2;
            ldm4(ah[mt], st + o2);
        }
        #pragma unroll
        for (int mt = 0; mt < 2; mt++)
            #pragma unroll
            for (int nt = 0; nt < 8; nt++)
                mma_hf(acc[mt][nt], ah[mt], bb[nt >> 1][(nt & 1) * 2], bb[nt >> 1][(nt & 1) * 2 + 1]);
        if (Al) {
            uint32_t al[2][4];
            #pragma unroll
            for (int mt = 0; mt < 2; mt++) {
                uint32_t o2 = (uint32_t)((a_row + mt * 16) * SM_STRIDE + ks * 16 + a_kc) * 2;
                ldm4(al[mt], st + 2560 * 2 + o2);
            }
            #pragma unroll
            for (int mt = 0; mt < 2; mt++)
                #pragma unroll
                for (int nt = 0; nt < 8; nt++)
                    mma_hf(acc[mt][nt], al[mt], bb[nt >> 1][(nt & 1) * 2], bb[nt >> 1][(nt & 1) * 2 + 1]);
        }
    };

    issue(0);
    for (int c = 0; c < NC; c++) {
        asm volatile("cp.async.wait_group 0;" ::: "memory");
        __syncthreads();
        const uint32_t st = sbase + (uint32_t)(c & 1) * (STAGE_ELE * 2);
        compute_ks(st, 0);
        if (c + 1 < NC) issue(c + 1);
        compute_ks(st, 1);
        __syncthreads();
    }

    #pragma unroll
    for (int mt = 0; mt < 2; mt++) {
        int rb = bm + warpM * 32 + mt * 16 + (lane >> 2);
        #pragma unroll
        for (int half = 0; half < 2; half++) {
            int rr = rb + half * 8;
            if (rr >= M) continue;
            #pragma unroll
            for (int nt = 0; nt < 8; nt++) {
                int col = bn + warpN * 64 + nt * 8 + ((lane & 3) << 1);
                size_t o = (size_t)rr * Nn + col;
                if (nsplit > 1) {
                    *(float2*)(part + (size_t)kz * ((size_t)T_TOT * Nn) + o) =
                        make_float2(acc[mt][nt][half * 2 + 0], acc[mt][nt][half * 2 + 1]);
                    continue;
                }
                float v0 = acc[mt][nt][half * 2 + 0] + bias[col];
                float v1 = acc[mt][nt][half * 2 + 1] + bias[col + 1];
                if (act) { v0 = v0 * normcdff(v0); v1 = v1 * normcdff(v1); }
                if (Ch) {
                    __half h0 = __float2half_rn(v0), h1 = __float2half_rn(v1);
                    *(uint32_t*)(Ch + o) = (uint32_t)__half_as_ushort(h0) | ((uint32_t)__half_as_ushort(h1) << 16);
                    if (Cl) *(uint32_t*)(Cl + o) = pack_hf2(v0 - __half2float(h0), v1 - __half2float(h1));
                } else {
                    *(float2*)(Cf + o) = make_float2(v0, v1);
                }
            }
        }
    }
}

// ---------------- QKV post: combine 3 partials + bias, RMS norm + RoPE ----------------
__global__ void qkvpost_kernel(const float* __restrict__ part, const float* __restrict__ qb,
                               const float* __restrict__ qn, const float* __restrict__ kn,
                               const float* __restrict__ rc, const float* __restrict__ rs,
                               __half* __restrict__ Qh, __half* __restrict__ Ql,
                               __half* __restrict__ Kh, __half* __restrict__ Vh,
                               int posmod)
{
    int gw = (blockIdx.x * blockDim.x + threadIdx.x) >> 5;
    int lane = threadIdx.x & 31;
    int t = gw / NHEAD, h = gw - (gw / NHEAD) * NHEAD;
    if (t >= T_TOT) return;
    const float* r0 = part + (size_t)t * 2304 + h * 64;
    const float* r1 = r0 + QKV_PART_STRIDE;
    const float* r2 = r1 + QKV_PART_STRIDE;
    const float* bb = qb + h * 64;
    float q0 = r0[lane] + r1[lane] + r2[lane] + bb[lane];
    float q1 = r0[lane + 32] + r1[lane + 32] + r2[lane + 32] + bb[lane + 32];
    float k0 = r0[768 + lane] + r1[768 + lane] + r2[768 + lane] + qb[768 + h * 64 + lane];
    float k1 = r0[768 + lane + 32] + r1[768 + lane + 32] + r2[768 + lane + 32] + qb[768 + h * 64 + lane + 32];
    float v0 = r0[1536 + lane] + r1[1536 + lane] + r2[1536 + lane] + qb[1536 + h * 64 + lane];
    float v1 = r0[1536 + lane + 32] + r1[1536 + lane + 32] + r2[1536 + lane + 32] + qb[1536 + h * 64 + lane + 32];
    float sq = q0 * q0 + q1 * q1, sk = k0 * k0 + k1 * k1;
    #pragma unroll
    for (int off = 16; off; off >>= 1) {
        sq += __shfl_xor_sync(0xffffffffu, sq, off);
        sk += __shfl_xor_sync(0xffffffffu, sk, off);
    }
    float rq = rsqrtf(sq * (1.f / 64.f) + 1e-6f);
    float rk = rsqrtf(sk * (1.f / 64.f) + 1e-6f);
    q0 *= rq * qn[lane]; q1 *= rq * qn[lane + 32];
    k0 *= rk * kn[lane]; k1 *= rk * kn[lane + 32];
    int pos = t % posmod;
    const float* cr = rc + (size_t)pos * 64;
    const float* sr = rs + (size_t)pos * 64;
    float c0 = cr[lane], c1 = cr[lane + 32];
    float s0 = sr[lane], s1 = sr[lane + 32];
    float sgn = (lane < 16) ? -1.f : 1.f;
    float qp0 = __shfl_xor_sync(0xffffffffu, q0, 16);
    float qp1 = __shfl_xor_sync(0xffffffffu, q1, 16);
    float kp0 = __shfl_xor_sync(0xffffffffu, k0, 16);
    float kp1 = __shfl_xor_sync(0xffffffffu, k1, 16);
    float qo0 = (q0 * c0 + sgn * qp0 * s0) * 0.125f;
    float qo1 = (q1 * c1 + sgn * qp1 * s1) * 0.125f;
    float ko0 = k0 * c0 + sgn * kp0 * s0;
    float ko1 = k1 * c1 + sgn * kp1 * s1;
    size_t base = ((size_t)h * T_TOT + t) * 64;
    __half hh;
    hh = __float2half_rn(qo0); Qh[base + lane] = hh;      Ql[base + lane]      = __float2half_rn(qo0 - __half2float(hh));
    hh = __float2half_rn(qo1); Qh[base + 32 + lane] = hh; Ql[base + 32 + lane] = __float2half_rn(qo1 - __half2float(hh));
    Kh[base + lane]      = __float2half_rn(ko0);
    Kh[base + 32 + lane] = __float2half_rn(ko1);
    Vh[base + lane]      = __float2half_rn(v0);
    Vh[base + 32 + lane] = __float2half_rn(v1);
}

// ---------------- fp16 tensor-core flash attention (1-term O output) ----------------
#define ATT_STRIDE 72
#define A_QH 0
#define A_QL 4608
#define A_STG 9216
#define A_STG_ELE 9216
#define ATT_SMEM (27648 * 2)

__global__ __launch_bounds__(128) void attn_mma(
    const __half* __restrict__ Qh, const __half* __restrict__ Ql,
    const __half* __restrict__ Kh, const __half* __restrict__ Vh,
    const float* __restrict__ kvmask,
    __half* __restrict__ Oh, int nq)
{
    extern __shared__ __align__(16) uint16_t smA[];
    const int tid = threadIdx.x, wid = tid >> 5, lane = tid & 31;
    const int qt = blockIdx.x, h = blockIdx.y, z = blockIdx.z;
    const int t0 = z * nq;
    const size_t hb = (size_t)h * T_TOT * 64;
    const uint32_t sbase = smem_u32(smA);
    const float* kvrow = kvmask + (size_t)z * nq;

    for (int i = tid; i < 512; i += 128) {
        int r = i >> 3, sg = i & 7;
        int qrow = qt * 64 + r;
        uint4 vh = make_uint4(0, 0, 0, 0), vl = make_uint4(0, 0, 0, 0);
        if (qrow < nq) {
            size_t go = hb + (size_t)(t0 + qrow) * 64 + sg * 8;
            vh = *(const uint4*)(Qh + go);
            vl = *(const uint4*)(Ql + go);
        }
        *(uint4*)((char*)smA + (A_QH + r * ATT_STRIDE + sg * 8) * 2) = vh;
        *(uint4*)((char*)smA + (A_QL + r * ATT_STRIDE + sg * 8) * 2) = vl;
    }
    __syncthreads();

    uint32_t qhf[4][4], qlf[4][4];
    {
        int arow = wid * 16 + (lane & 15);
        int akc = (lane >> 4) * 8;
        #pragma unroll
        for (int kc = 0; kc < 4; kc++) {
            uint32_t off = (uint32_t)(arow * ATT_STRIDE + kc * 16 + akc) * 2;
            ldm4(qhf[kc], sbase + A_QH * 2 + off);
            ldm4(qlf[kc], sbase + A_QL * 2 + off);
        }
    }

    auto stage_load = [&](int kt) {
        int s = kt & 1;
        uint32_t sb = sbase + (uint32_t)(A_STG + s * A_STG_ELE) * 2;
        int kbase = kt * 64;
        #pragma unroll
        for (int it = 0; it < 8; it++) {
            int i = tid + it * 128;
            int m = i >> 9, v = i & 511, r = v >> 3, sg = v & 7;
            int key = kbase + r;
            int sz = 16;
            if (key >= nq) { sz = 0; key = nq - 1; }
            const __half* gp = (m == 0 ? Kh : Vh) + hb + (size_t)(t0 + key) * 64 + sg * 8;
            uint32_t da = sb + (uint32_t)(m * 4608 + r * ATT_STRIDE + sg * 8) * 2;
            asm volatile("cp.async.cg.shared.global [%0], [%1], 16, %2;"
                         :: "r"(da), "l"(gp), "r"(sz));
        }
        asm volatile("cp.async.commit_group;" ::: "memory");
    };

    float o[8][4];
    #pragma unroll
    for (int i = 0; i < 8; i++)
        #pragma unroll
        for (int j = 0; j < 4; j++) o[i][j] = 0.f;
    float m0 = -1e30f, m1 = -1e30f, l0 = 0.f, l1 = 0.f;

    const int nkt = (nq + 63) >> 6;
    const int brow = ((lane >> 4) & 1) * 8 + (lane & 7);
    const int bkc = ((lane >> 3) & 1) * 8;
    const int vr0 = ((lane >> 3) & 1) * 8 + (lane & 7);
    const int vc0 = (lane >> 4) * 8;

    stage_load(0);
    for (int kt = 0; kt < nkt; kt++) {
        if (kt + 1 < nkt) {
            stage_load(kt + 1);
            asm volatile("cp.async.wait_group 1;" ::: "memory");
        } else {
            asm volatile("cp.async.wait_group 0;" ::: "memory");
        }
        __syncthreads();
        uint32_t sb = sbase + (uint32_t)(A_STG + (kt & 1) * A_STG_ELE) * 2;
        int kbase = kt * 64;

        float s_[8][4];
        #pragma unroll
        for (int nt = 0; nt < 8; nt++) {
            int key = kbase + nt * 8 + ((lane & 3) << 1);
            float b0 = (key < nq) ? (1.f - kvrow[key]) * -10000.f : -1e30f;
            float b1 = (key + 1 < nq) ? (1.f - kvrow[key + 1]) * -10000.f : -1e30f;
            s_[nt][0] = b0; s_[nt][1] = b1; s_[nt][2] = b0; s_[nt][3] = b1;
        }
        #pragma unroll
        for (int np = 0; np < 4; np++) {
            #pragma unroll
            for (int kc = 0; kc < 4; kc++) {
                uint32_t off = (uint32_t)((np * 16 + brow) * ATT_STRIDE + kc * 16 + bkc) * 2;
                uint32_t kh4[4];
                ldm4(kh4, sb + off);
                mma_hf(s_[2 * np],     qhf[kc], kh4[0], kh4[1]);
                mma_hf(s_[2 * np + 1], qhf[kc], kh4[2], kh4[3]);
                mma_hf(s_[2 * np],     qlf[kc], kh4[0], kh4[1]);
                mma_hf(s_[2 * np + 1], qlf[kc], kh4[2], kh4[3]);
            }
        }
        float mx0 = -1e30f, mx1 = -1e30f;
        #pragma unroll
        for (int nt = 0; nt < 8; nt++) {
            mx0 = fmaxf(mx0, fmaxf(s_[nt][0], s_[nt][1]));
            mx1 = fmaxf(mx1, fmaxf(s_[nt][2], s_[nt][3]));
        }
        mx0 = fmaxf(mx0, __shfl_xor_sync(0xffffffffu, mx0, 1));
        mx0 = fmaxf(mx0, __shfl_xor_sync(0xffffffffu, mx0, 2));
        mx1 = fmaxf(mx1, __shfl_xor_sync(0xffffffffu, mx1, 1));
        mx1 = fmaxf(mx1, __shfl_xor_sync(0xffffffffu, mx1, 2));
        float mn0 = fmaxf(m0, mx0), mn1 = fmaxf(m1, mx1);
        float sc0 = __expf(m0 - mn0), sc1 = __expf(m1 - mn1);
        m0 = mn0; m1 = mn1;
        float ps0 = 0.f, ps1 = 0.f;
        #pragma unroll
        for (int nt = 0; nt < 8; nt++) {
            s_[nt][0] = __expf(s_[nt][0] - mn0); ps0 += s_[nt][0];
            s_[nt][1] = __expf(s_[nt][1] - mn0); ps0 += s_[nt][1];
            s_[nt][2] = __expf(s_[nt][2] - mn1); ps1 += s_[nt][2];
            s_[nt][3] = __expf(s_[nt][3] - mn1); ps1 += s_[nt][3];
        }
        ps0 += __shfl_xor_sync(0xffffffffu, ps0, 1);
        ps0 += __shfl_xor_sync(0xffffffffu, ps0, 2);
        ps1 += __shfl_xor_sync(0xffffffffu, ps1, 1);
        ps1 += __shfl_xor_sync(0xffffffffu, ps1, 2);
        l0 = l0 * sc0 + ps0;
        l1 = l1 * sc1 + ps1;
        #pragma unroll
        for (int nt = 0; nt < 8; nt++) {
            o[nt][0] *= sc0; o[nt][1] *= sc0; o[nt][2] *= sc1; o[nt][3] *= sc1;
        }
        uint32_t pfh[4][4], pfl[4][4];
        #pragma unroll
        for (int kc = 0; kc < 4; kc++) {
            #pragma unroll
            for (int q = 0; q < 4; q++) {
                float a = s_[2 * kc + (q >> 1)][(q & 1) * 2];
                float b = s_[2 * kc + (q >> 1)][(q & 1) * 2 + 1];
                __half ha = __float2half_rn(a), hb2 = __float2half_rn(b);
                pfh[kc][q] = (uint32_t)__half_as_ushort(ha) | ((uint32_t)__half_as_ushort(hb2) << 16);
                pfl[kc][q] = pack_hf2(a - __half2float(ha), b - __half2float(hb2));
            }
        }
        #pragma unroll
        for (int kc = 0; kc < 4; kc++) {
            #pragma unroll
            for (int dp = 0; dp < 4; dp++) {
                uint32_t off = (uint32_t)((kc * 16 + vr0) * ATT_STRIDE + dp * 16 + vc0) * 2;
                uint32_t vh4[4];
                ldm4t(vh4, sb + 4608 * 2 + off);
                mma_hf(o[2 * dp],     pfh[kc], vh4[0], vh4[1]);
                mma_hf(o[2 * dp + 1], pfh[kc], vh4[2], vh4[3]);
                mma_hf(o[2 * dp],     pfl[kc], vh4[0], vh4[1]);
                mma_hf(o[2 * dp + 1], pfl[kc], vh4[2], vh4[3]);
            }
        }
        __syncthreads();
    }

    float inv0 = 1.f / l0, inv1 = 1.f / l1;
    int r = lane >> 2;
    int q0row = qt * 64 + wid * 16 + r;
    int q1row = q0row + 8;
    #pragma unroll
    for (int nt = 0; nt < 8; nt++) {
        int d = nt * 8 + ((lane & 3) << 1);
        if (q0row < nq) {
            size_t ob = (size_t)(t0 + q0row) * C_DIM + h * 64 + d;
            *(uint32_t*)(Oh + ob) = pack_hf2(o[nt][0] * inv0, o[nt][1] * inv0);
        }
        if (q1row < nq) {
            size_t ob = (size_t)(t0 + q1row) * C_DIM + h * 64 + d;
            *(uint32_t*)(Oh + ob) = pack_hf2(o[nt][2] * inv1, o[nt][3] * inv1);
        }
    }
}

// ---------------- emit output ----------------
__global__ __launch_bounds__(256) void emit_kernel(const float* __restrict__ xloc, const float* __restrict__ xg,
                                                   const float* __restrict__ fw, const float* __restrict__ fb,
                                                   float* __restrict__ out)
{
    __shared__ float sh[8];
    int row = blockIdx.x;
    int s = row / 576, n = row - s * 576 + 1;
    int t = s * 577 + n;
    int tid = threadIdx.x;
    const float* xr = xg + (size_t)t * C_DIM;
    float v0 = xr[tid], v1 = xr[tid + 256], v2 = xr[tid + 512];
    float mean = block_sum_256(v0 + v1 + v2, sh) * (1.f / 768.f);
    float d0 = v0 - mean, d1 = v1 - mean, d2 = v2 - mean;
    float var = block_sum_256(d0 * d0 + d1 * d1 + d2 * d2, sh) * (1.f / 768.f);
    float rstd = rsqrtf(var + 1e-6f);
    const float* lr = xloc + (size_t)t * C_DIM;
    float* orow = out + (size_t)row * 1536;
    orow[tid]       = lr[tid];
    orow[tid + 256] = lr[tid + 256];
    orow[tid + 512] = lr[tid + 512];
    orow[768 + tid]       = d0 * rstd * fw[tid]       + fb[tid];
    orow[768 + tid + 256] = d1 * rstd * fw[tid + 256] + fb[tid + 256];
    orow[768 + tid + 512] = d2 * rstd * fw[tid + 512] + fb[tid + 512];
}

__global__ void cam_kernel(const float* __restrict__ xloc, const float* __restrict__ xg,
                           float* __restrict__ out) {
    int s = blockIdx.x;
    int t = s * 577;
    for (int c = threadIdx.x; c < C_DIM; c += 256) {
        out[s * 1536 + c]       = xloc[(size_t)t * C_DIM + c];
        out[s * 1536 + 768 + c] = xg[(size_t)t * C_DIM + c];
    }
}

// ---------------- host orchestration ----------------
extern "C" void kernel_launch(void* const* d_in, const int* in_sizes, int n_in,
                              void* d_out, int out_size)
{
    const float* x_in  = (const float*)d_in[0];
    const float* rc_l  = (const float*)d_in[1];
    const float* rs_l  = (const float*)d_in[2];
    const float* rc_g  = (const float*)d_in[3];
    const float* rs_g  = (const float*)d_in[4];
    const float* kv_l  = (const float*)d_in[5];
    const float* kv_g  = (const float*)d_in[6];
    const float* cam   = (const float*)d_in[7];
    const float* qkv_w = (const float*)d_in[8];
    const float* qkv_b = (const float*)d_in[9];
    const float* qn_w  = (const float*)d_in[10];
    const float* kn_w  = (const float*)d_in[11];
    const float* pw    = (const float*)d_in[12];
    const float* pb    = (const float*)d_in[13];
    const float* g1    = (const float*)d_in[14];
    const float* g2    = (const float*)d_in[15];
    const float* n1w   = (const float*)d_in[16];
    const float* n1b   = (const float*)d_in[17];
    const float* n2w   = (const float*)d_in[18];
    const float* n2b   = (const float*)d_in[19];
    const float* f1w   = (const float*)d_in[20];
    const float* f1b   = (const float*)d_in[21];
    const float* f2w   = (const float*)d_in[22];
    const float* f2b   = (const float*)d_in[23];
    const float* fnw   = (const float*)d_in[24];
    const float* fnb   = (const float*)d_in[25];
    float* out = (float*)d_out;

    float *p_x, *p_loc, *p_part;
    __half *p_w, *p_sh, *p_sl, *p_mh, *p_qh, *p_ql, *p_kh, *p_vh;
    cudaGetSymbolAddress((void**)&p_x,   g_x);
    cudaGetSymbolAddress((void**)&p_loc, g_loc);
    cudaGetSymbolAddress((void**)&p_part, g_part);
    cudaGetSymbolAddress((void**)&p_w,   g_w);
    cudaGetSymbolAddress((void**)&p_sh,  g_sh);
    cudaGetSymbolAddress((void**)&p_sl,  g_sl);
    cudaGetSymbolAddress((void**)&p_mh,  g_mh);
    cudaGetSymbolAddress((void**)&p_qh,  g_qh);
    cudaGetSymbolAddress((void**)&p_ql,  g_ql);
    cudaGetSymbolAddress((void**)&p_kh,  g_kh);
    cudaGetSymbolAddress((void**)&p_vh,  g_vh);

    cudaFuncSetAttribute(gemm_mma, cudaFuncAttributeMaxDynamicSharedMemorySize, GEMM_SMEM);
    cudaFuncSetAttribute(attn_mma, cudaFuncAttributeMaxDynamicSharedMemorySize, ATT_SMEM);

    const int eb = (NE + 255) / 256;
    convall_kernel<<<(W_TOTAL / 4 + 255) / 256, 256>>>(qkv_w, pw, f1w, f2w, p_w);
    init_x_kernel<<<eb, 256>>>(x_in, cam);

    const int MT = (T_TOT + 63) / 64;   // 19 M-tiles
    int outidx = 0;
    for (int i = 0; i < 12; i++) {
        bool isg = (i & 1);
        int nb = isg ? 1 : 2;
        int nq = isg ? 1154 : 577;
        const float* rc = isg ? rc_g : rc_l;
        const float* rs = isg ? rs_g : rs_l;
        const float* kv = isg ? kv_g : kv_l;

        if (i == 0)
            ln_kernel<<<T_TOT, 256>>>(p_x, p_sh, p_sl, n1w, n1b);
        // QKV: 2-term activations, split-K=3
        gemm_mma<<<dim3(18, MT, 3), 128, GEMM_SMEM>>>(
            p_sh, p_sl, p_w + W_QKV_OFF + (size_t)i * 2304 * 768,
            nullptr, nullptr, nullptr, nullptr, p_part, T_TOT, 2304, 768, 0, 3);
        qkvpost_kernel<<<(T_TOT * NHEAD * 32 + 127) / 128, 128>>>(
            p_part, qkv_b + i * 2304, qn_w + i * 64, kn_w + i * 64, rc, rs,
            p_qh, p_ql, p_kh, p_vh, nq);
        attn_mma<<<dim3((nq + 63) / 64, NHEAD, nb), 128, ATT_SMEM>>>(
            p_qh, p_ql, p_kh, p_vh, kv, p_sh, nq);
        // proj: 1-term A (attention Oh), split-K=3
        gemm_mma<<<dim3(6, MT, 3), 128, GEMM_SMEM>>>(
            p_sh, nullptr, p_w + W_PROJ_OFF + (size_t)i * 768 * 768,
            nullptr, nullptr, nullptr, nullptr, p_part, T_TOT, 768, 768, 0, 3);
        combine_ln_kernel<<<T_TOT, 256>>>(p_x, p_part, pb + i * 768, g1 + i * 768, 3,
                                          n2w + i * 768, n2b + i * 768, p_sh, nullptr, nullptr);
        // fc1: 1-term A, direct epilogue (bias+GELU), hi-only output
        gemm_mma<<<dim3(24, MT, 1), 128, GEMM_SMEM>>>(
            p_sh, nullptr, p_w + W_FC1_OFF + (size_t)i * 3072 * 768,
            f1b + i * 3072, nullptr, p_mh, nullptr, nullptr, T_TOT, 3072, 768, 1, 1);
        // fc2: 1-term A, split-K=3
        gemm_mma<<<dim3(6, MT, 3), 128, GEMM_SMEM>>>(
            p_mh, nullptr, p_w + W_FC2_OFF + (size_t)i * 768 * 3072,
            nullptr, nullptr, nullptr, nullptr, p_part, T_TOT, 768, 3072, 0, 3);
        if (i < 11) {
            float* locp = (i == 4 || i == 10) ? p_loc : nullptr;
            combine_ln_kernel<<<T_TOT, 256>>>(p_x, p_part, f2b + i * 768, g2 + i * 768, 3,
                                              n1w + (i + 1) * 768, n1b + (i + 1) * 768, p_sh, p_sl, locp);
        } else {
            combine_kernel<<<eb, 256>>>(p_x, p_part, f2b + i * 768, g2 + i * 768, 3);
        }

        if (i == 2 || i == 5 || i == 8 || i == 11) {
            const float* loc = (i == 5 || i == 11) ? p_loc : p_x;
            emit_kernel<<<1152, 256>>>(loc, p_x, fnw, fnb, out + (size_t)outidx * 1769472);
            if (i == 11) cam_kernel<<<2, 256>>>(loc, p_x, out + 4ull * 1769472);
            outidx++;
        }
    }
}